// round 15
// baseline (speedup 1.0000x reference)
#include <cuda_runtime.h>
#include <cuda_bf16.h>
#include <math.h>

// Problem constants (fixed shapes): B=16, N=2000, C=512, H=W=7
#define Bn 16
#define Nn 2000
#define Dn 25088            // 512*7*7
#define PI2F ((float)(3.14159 / 2.0))   // matches reference constant exactly
#define CHUNK 256           // floats per d-chunk in k_dots
#define DSPLIT 7            // d-split for k_dots
#define CPB 14              // chunks per block = (25088/256)/7
#define WSLOT 1536          // floats per warp per slot (512 key + 1024 mem)
#define RSTG 12             // k_read pipeline stages

// ---- device scratch (static allocation only; no cudaMalloc allowed) ----
__device__ float  g_dotp[DSPLIT * Bn * Nn];  // partial dots per d-split, [p][b][n]
__device__ float  g_sqp[DSPLIT * Nn];        // partial row sumsq per d-split, [p][n]
__device__ __align__(16) float2 g_w2[Nn * Bn];  // weights, [n][b], duplicated (w,w)

// ---- packed fp32x2 FMA (sm_100+; ptxas will not auto-generate this) ----
__device__ __forceinline__ void fma2(unsigned long long& acc,
                                     unsigned long long a,
                                     unsigned long long b) {
    asm("fma.rn.f32x2 %0, %1, %2, %0;" : "+l"(acc) : "l"(a), "l"(b));
}
__device__ __forceinline__ float f2lo(unsigned long long v) {
    return __uint_as_float((unsigned)(v & 0xFFFFFFFFull));
}
__device__ __forceinline__ float f2hi(unsigned long long v) {
    return __uint_as_float((unsigned)(v >> 32));
}

// ---- cp.async (LDGSTS) helpers ----
__device__ __forceinline__ void cp16(void* smem, const void* gmem) {
    unsigned s = (unsigned)__cvta_generic_to_shared(smem);
    asm volatile("cp.async.cg.shared.global [%0], [%1], 16;" :: "r"(s), "l"(gmem));
}
__device__ __forceinline__ void cp_commit() {
    asm volatile("cp.async.commit_group;");
}
template <int N>
__device__ __forceinline__ void cp_wait() {
    asm volatile("cp.async.wait_group %0;" :: "n"(N));
}

// ---- no-return vector atomic add ----
__device__ __forceinline__ void red_add4(float* p, float x, float y, float z, float w) {
    asm volatile("red.global.add.v4.f32 [%0], {%1, %2, %3, %4};"
                 :: "l"(p), "f"(x), "f"(y), "f"(z), "f"(w) : "memory");
}

// =======================================================================
// K2: partial dots + partial sumsq. grid (125, 7) x 256 threads.
// Block owns 16 memory rows, 14 d-chunks of 256 floats (d-split by grid.y).
// WARP-PRIVATE pipelines: warp w=(bh,u_hi) stages exactly its own slice of
// each chunk — key rows bh*8..+7 and mem rows 0..15, columns
// [u_hi*32, +32) in each 128-float half — into a private 2-slot smem ring
// (6KB/warp/slot). One commit + one wait<1> per chunk per warp; NO
// __syncthreads in the main loop, so warps never resynchronize and each
// runs a k_read-style private prefetch pipeline.
// Dynamic smem: 2 slots x 8 warps x 6KB = 96KB; 2 blocks/SM.
// Lane layout per warp: bits[4:3]=g (which 4 n's), bits[2:0]=u_lo.
// Mem slices are staged by both bh warps (2nd LDGSTS hits same L2 lines).
// =======================================================================
__global__ __launch_bounds__(256, 2) void k_dots(const float* __restrict__ key,
                                                 const float* __restrict__ mem) {
    extern __shared__ __align__(16) float sdyn[];   // 2 * 8 * WSLOT floats
    float* sred = sdyn;          // overlay after loop: 256 floats [bh][g][bb][r]
    float* ssq  = sdyn + 256;    // overlay: 16 floats [g][r]

    int tid  = threadIdx.x;
    int wid  = tid >> 5;          // warp 0..7
    int lane = tid & 31;
    int bh   = wid >> 2;          // which 8 b's
    int u_hi = wid & 3;           // which 32-float column quarter
    int g    = (lane >> 3) & 3;   // which 4 n's
    int u_lo = lane & 7;
    int nb   = blockIdx.x * 16;
    int sy   = blockIdx.y;
    size_t cbase = (size_t)sy * CPB * CHUNK;

    unsigned long long acc[8][4];
    #pragma unroll
    for (int i = 0; i < 8; ++i)
        #pragma unroll
        for (int r = 0; r < 4; ++r) acc[i][r] = 0ull;
    unsigned long long sq2[4] = {0ull, 0ull, 0ull, 0ull};

    // ---- warp-private staging lane map ----
    // key: 4 cp16/lane: f = lane + 32k, k=0..3 (f in [0,128))
    //   row=f>>4 (0..7), half=(f>>3)&1, q=f&7
    // mem: 8 cp16/lane: f = lane + 32k, k=0..7 (f in [0,256))
    //   row=f>>4 (0..15), half, q
    // gmem col = chunk*256 + half*128 + u_hi*32 + q*4
    // smem (floats, within warp slot): key row*64 + half*32 + q*4
    //                                  mem 512 + row*64 + half*32 + q*4
    const float* gk[4];
    int sk[4];
    #pragma unroll
    for (int k = 0; k < 4; ++k) {
        int f = lane + 32 * k, row = f >> 4, half = (f >> 3) & 1, q = f & 7;
        gk[k] = key + (size_t)(bh * 8 + row) * Dn + cbase
                    + half * 128 + u_hi * 32 + q * 4;
        sk[k] = row * 64 + half * 32 + q * 4;
    }
    const float* gm[8];
    int sm[8];
    #pragma unroll
    for (int k = 0; k < 8; ++k) {
        int f = lane + 32 * k, row = f >> 4, half = (f >> 3) & 1, q = f & 7;
        gm[k] = mem + (size_t)(nb + row) * Dn + cbase
                    + half * 128 + u_hi * 32 + q * 4;
        sm[k] = 512 + row * 64 + half * 32 + q * 4;
    }

    float* w0 = sdyn + wid * WSLOT;             // slot 0 warp region
    float* w1 = sdyn + 8 * WSLOT + wid * WSLOT; // slot 1 warp region

    // per-thread constant compute offsets within warp region
    int mvoff = 512 + g * 4 * 64 + u_lo * 4;    // + r*64 + h*32
    int kvoff = u_lo * 4;                        // + bb*64 + h*32

    // prologue: stage chunk 0 into slot 0
    #pragma unroll
    for (int k = 0; k < 4; ++k) cp16(w0 + sk[k], gk[k]);
    #pragma unroll
    for (int k = 0; k < 8; ++k) cp16(w0 + sm[k], gm[k]);
    cp_commit();
    #pragma unroll
    for (int k = 0; k < 4; ++k) gk[k] += CHUNK;
    #pragma unroll
    for (int k = 0; k < 8; ++k) gm[k] += CHUNK;

    #pragma unroll 1
    for (int cc = 0; cc < CPB; ++cc) {
        // stage chunk cc+1 into the other slot (this warp finished it at cc-1)
        if (cc + 1 < CPB) {
            float* wn = ((cc + 1) & 1) ? w1 : w0;
            #pragma unroll
            for (int k = 0; k < 4; ++k) cp16(wn + sk[k], gk[k]);
            #pragma unroll
            for (int k = 0; k < 8; ++k) cp16(wn + sm[k], gm[k]);
            #pragma unroll
            for (int k = 0; k < 4; ++k) gk[k] += CHUNK;
            #pragma unroll
            for (int k = 0; k < 8; ++k) gm[k] += CHUNK;
        }
        cp_commit();           // unconditional: keeps group accounting
        cp_wait<1>();          // chunk cc landed (cc+1 still in flight)
        __syncwarp();

        const float* wc = (cc & 1) ? w1 : w0;
        #pragma unroll
        for (int h = 0; h < 2; ++h) {          // two 128-float halves
            const int hb = h * 32;
            ulonglong2 mv[4];
            #pragma unroll
            for (int r = 0; r < 4; ++r)
                mv[r] = *(const ulonglong2*)&wc[mvoff + r * 64 + hb];
            if (bh == 0) {
                #pragma unroll
                for (int r = 0; r < 4; ++r) {
                    fma2(sq2[r], mv[r].x, mv[r].x);
                    fma2(sq2[r], mv[r].y, mv[r].y);
                }
            }
            #pragma unroll
            for (int bb = 0; bb < 8; ++bb) {
                ulonglong2 kv = *(const ulonglong2*)&wc[kvoff + bb * 64 + hb];
                #pragma unroll
                for (int r = 0; r < 4; ++r) {
                    fma2(acc[bb][r], kv.x, mv[r].x);
                    fma2(acc[bb][r], kv.y, mv[r].y);
                }
            }
        }
    }
    cp_wait<0>();      // drain trailing empty group
    __syncthreads();   // all warps done; safe to overlay reduction scratch
    sred[tid] = 0.f;
    if (tid < 16) ssq[tid] = 0.f;
    __syncthreads();

    // reduce: butterfly over u_lo (8 lanes), then smem-atomic across 4 u_hi warps
    #pragma unroll
    for (int bb = 0; bb < 8; ++bb)
        #pragma unroll
        for (int r = 0; r < 4; ++r) {
            float v = f2lo(acc[bb][r]) + f2hi(acc[bb][r]);
            v += __shfl_xor_sync(0xFFFFFFFFu, v, 1);
            v += __shfl_xor_sync(0xFFFFFFFFu, v, 2);
            v += __shfl_xor_sync(0xFFFFFFFFu, v, 4);
            if (bb == u_lo)
                atomicAdd(&sred[bh * 128 + g * 32 + bb * 4 + r], v);
        }
    if (bh == 0) {
        #pragma unroll
        for (int r = 0; r < 4; ++r) {
            float v = f2lo(sq2[r]) + f2hi(sq2[r]);
            v += __shfl_xor_sync(0xFFFFFFFFu, v, 1);
            v += __shfl_xor_sync(0xFFFFFFFFu, v, 2);
            v += __shfl_xor_sync(0xFFFFFFFFu, v, 4);
            if (u_lo == r) atomicAdd(&ssq[g * 4 + r], v);
        }
    }
    __syncthreads();

    {   // write 256 partial dots
        int r = tid & 3, bb = (tid >> 2) & 7, gg = (tid >> 5) & 3, b2 = tid >> 7;
        int b = b2 * 8 + bb, n = nb + gg * 4 + r;
        g_dotp[((size_t)sy * Bn + b) * Nn + n] = sred[b2 * 128 + gg * 32 + bb * 4 + r];
    }
    if (tid < 16) {
        int r = tid & 3, gg = tid >> 2;
        g_sqp[(size_t)sy * Nn + nb + gg * 4 + r] = ssq[gg * 4 + r];
    }
}

// ============================================================
// K3: key stats (block b reduces its own key row) -> sum dot
// partials -> cos -> tan -> softmax; write transposed duplicated
// weights (w,w). Also zeroes d_out. grid 16 x 256.
// ============================================================
__global__ void k_softmax(const float* __restrict__ key, float* __restrict__ out) {
    int b = blockIdx.x, tid = threadIdx.x;
    __shared__ float sbuf[256];
    __shared__ float swq[8], sws[8];
    __shared__ float s_kfac;

    // zero this block's slice of the output (Bn*Dn floats over 16 blocks)
    {
        float4 z = make_float4(0.f, 0.f, 0.f, 0.f);
        float4* o4 = (float4*)(out + (size_t)b * Dn);
        for (int i = tid; i < Dn / 4; i += 256) o4[i] = z;
    }

    // key stats: sum and sumsq of key row b (6272 float4)
    {
        const float4* kp = (const float4*)(key + (size_t)b * Dn);
        float s = 0.f, q = 0.f;
        for (int i = tid; i < Dn / 4; i += 256) {
            float4 v = kp[i];
            s += (v.x + v.y) + (v.z + v.w);
            q = fmaf(v.x, v.x, q); q = fmaf(v.y, v.y, q);
            q = fmaf(v.z, v.z, q); q = fmaf(v.w, v.w, q);
        }
        #pragma unroll
        for (int o = 16; o; o >>= 1) {
            s += __shfl_xor_sync(0xFFFFFFFFu, s, o);
            q += __shfl_xor_sync(0xFFFFFFFFu, q, o);
        }
        if ((tid & 31) == 0) { sws[tid >> 5] = s; swq[tid >> 5] = q; }
        __syncthreads();
        if (tid == 0) {
            float S = 0.f, Q = 0.f;
            #pragma unroll
            for (int i = 0; i < 8; ++i) { S += sws[i]; Q += swq[i]; }
            S += 1e-7f;                               // EPS_SUM
            // (s+eps)*kn = max(sqrt(sq_key), 1e-8*(s+eps))
            s_kfac = 1.f / fmaxf(sqrtf(Q), 1e-8f * S);
        }
        __syncthreads();
    }
    float kf = s_kfac;

    float tv[8];
    float mx = -3.4e38f;
    #pragma unroll
    for (int i = 0; i < 8; ++i) {
        int n = tid + i * 256;
        if (n < Nn) {
            float dot = 0.f, sqv = 0.f;
            #pragma unroll
            for (int p = 0; p < DSPLIT; ++p) {
                dot += g_dotp[((size_t)p * Bn + b) * Nn + n];
                sqv += g_sqp[(size_t)p * Nn + n];
            }
            float mn = fmaxf(sqrtf(sqv), 1e-8f);
            float cosv = dot * kf / mn;
            float t = tanf(cosv * PI2F);
            tv[i] = t;
            mx = fmaxf(mx, t);
        } else tv[i] = -3.4e38f;
    }
    sbuf[tid] = mx; __syncthreads();
    for (int s = 128; s; s >>= 1) {
        if (tid < s) sbuf[tid] = fmaxf(sbuf[tid], sbuf[tid + s]);
        __syncthreads();
    }
    mx = sbuf[0];
    __syncthreads();

    float sum = 0.f;
    #pragma unroll
    for (int i = 0; i < 8; ++i) {
        int n = tid + i * 256;
        if (n < Nn) { float e = expf(tv[i] - mx); tv[i] = e; sum += e; }
    }
    sbuf[tid] = sum; __syncthreads();
    for (int s = 128; s; s >>= 1) {
        if (tid < s) sbuf[tid] += sbuf[tid + s];
        __syncthreads();
    }
    float inv = 1.f / sbuf[0];

    #pragma unroll
    for (int i = 0; i < 8; ++i) {
        int n = tid + i * 256;
        if (n < Nn) {
            float w = tv[i] * inv;
            g_w2[(size_t)n * Bn + b] = make_float2(w, w);  // pre-duplicated pair
        }
    }
}

// =======================================================================
// K4: out[b][d] = sum_n w[b][n] * mem[n][d]. grid (49, 12) x 128 threads.
// 588 blocks = exactly one occ-4 wave (592 slots on 148 SMs).
// Thread owns 4 consecutive d; 16 b accumulators as f32x2 pairs.
// Mem rows flow through a per-thread 12-stage cp.async pipeline (11 rows of
// DRAM latency in flight, no barriers). Weight tile staged in smem once.
// Partials combined via red.global.add.v4.f32 (no-return vector atomic).
// =======================================================================
__global__ __launch_bounds__(128, 4) void k_read(const float* __restrict__ mem,
                                                 float* __restrict__ out) {
    __shared__ __align__(16) ulonglong2 sw[167 * 8];     // 21376 B weight tile
    __shared__ __align__(16) char smrow[RSTG][2048];     // 24 KB pipeline

    int tid = threadIdx.x;
    int d   = blockIdx.x * 512 + tid * 4;
    int y   = blockIdx.y;
    int n0  = (y < 8) ? y * 167 : 1336 + (y - 8) * 166;
    int cnt = (y < 8) ? 167 : 166;

    // stage weight tile: cnt x 128B
    {
        const float4* src = (const float4*)(g_w2 + (size_t)n0 * Bn);
        for (int i = tid; i < cnt * 8; i += 128)
            ((float4*)sw)[i] = src[i];
    }

    unsigned long long acc[16][2];
    #pragma unroll
    for (int b = 0; b < 16; ++b) { acc[b][0] = 0ull; acc[b][1] = 0ull; }

    const float* mp = mem + (size_t)n0 * Dn + d;
    // prologue: 11 rows in flight (cnt >= 166 always)
    #pragma unroll
    for (int s = 0; s < RSTG - 1; ++s) {
        cp16(&smrow[s][tid * 16], mp + (size_t)s * Dn);
        cp_commit();
    }
    const float* pf = mp + (size_t)(RSTG - 1) * Dn;
    __syncthreads();   // weight tile ready

    int slc = 0, sli = RSTG - 1;
    for (int n = 0; n < cnt; ++n) {
        cp_wait<RSTG - 2>();  // per-thread: stage n landed
        ulonglong2 cur = *(const ulonglong2*)&smrow[slc][tid * 16];
        if (++slc == RSTG) slc = 0;
        if (n + RSTG - 1 < cnt) cp16(&smrow[sli][tid * 16], pf);
        cp_commit();
        if (++sli == RSTG) sli = 0;
        pf += Dn;
        const ulonglong2* wq = sw + n * 8;
        #pragma unroll
        for (int q = 0; q < 8; ++q) {
            ulonglong2 wv = wq[q];                // (w2q,w2q),(w2q+1,w2q+1)
            fma2(acc[2 * q    ][0], wv.x, cur.x);
            fma2(acc[2 * q    ][1], wv.x, cur.y);
            fma2(acc[2 * q + 1][0], wv.y, cur.x);
            fma2(acc[2 * q + 1][1], wv.y, cur.y);
        }
    }

    #pragma unroll
    for (int b = 0; b < 16; ++b) {
        float* o = out + (size_t)b * Dn + d;
        red_add4(o, f2lo(acc[b][0]), f2hi(acc[b][0]),
                    f2lo(acc[b][1]), f2hi(acc[b][1]));
    }
}

// ============================================================
extern "C" void kernel_launch(void* const* d_in, const int* in_sizes, int n_in,
                              void* d_out, int out_size) {
    const float* key = (const float*)d_in[0];
    const float* mem = (const float*)d_in[1];
    // metadata order is key, memory; swap defensively if sizes say otherwise
    if (n_in >= 2 && in_sizes[0] == Nn * Dn) {
        key = (const float*)d_in[1];
        mem = (const float*)d_in[0];
    }
    float* out = (float*)d_out;

    // 96KB dynamic smem for k_dots (attribute persists from the harness's
    // non-captured correctness call, so capture-time behavior is identical)
    const int kdots_smem = 2 * 8 * WSLOT * (int)sizeof(float);
    cudaFuncSetAttribute(k_dots, cudaFuncAttributeMaxDynamicSharedMemorySize,
                         kdots_smem);

    k_dots<<<dim3(125, DSPLIT), 256, kdots_smem>>>(key, mem);
    k_softmax<<<16, 256>>>(key, out);  // key stats + softmax + zeroes out
    k_read<<<dim3(49, 12), 128>>>(mem, out);
}

// round 17
// speedup vs baseline: 1.0428x; 1.0428x over previous
#include <cuda_runtime.h>
#include <cuda_bf16.h>
#include <math.h>

// Problem constants (fixed shapes): B=16, N=2000, C=512, H=W=7
#define Bn 16
#define Nn 2000
#define Dn 25088            // 512*7*7
#define PI2F ((float)(3.14159 / 2.0))   // matches reference constant exactly
#define CHUNK 128           // floats per d-chunk in k_dots
#define DSPLIT 7            // d-split for k_dots
#define CPB 28              // chunks per block = (25088/128)/7
#define KSTG 5              // k_dots pipeline stages
#define RSTG 12             // k_read pipeline stages

// ---- device scratch (static allocation only; no cudaMalloc allowed) ----
__device__ float  g_dotp[DSPLIT * Bn * Nn];  // partial dots per d-split, [p][b][n]
__device__ float  g_sqp[DSPLIT * Nn];        // partial row sumsq per d-split, [p][n]
__device__ __align__(16) float2 g_w2[Nn * Bn];  // weights, [n][b], duplicated (w,w)

// ---- packed fp32x2 FMA (sm_100+; ptxas will not auto-generate this) ----
__device__ __forceinline__ void fma2(unsigned long long& acc,
                                     unsigned long long a,
                                     unsigned long long b) {
    asm("fma.rn.f32x2 %0, %1, %2, %0;" : "+l"(acc) : "l"(a), "l"(b));
}
__device__ __forceinline__ float f2lo(unsigned long long v) {
    return __uint_as_float((unsigned)(v & 0xFFFFFFFFull));
}
__device__ __forceinline__ float f2hi(unsigned long long v) {
    return __uint_as_float((unsigned)(v >> 32));
}

// ---- cp.async (LDGSTS) helpers ----
__device__ __forceinline__ void cp16(void* smem, const void* gmem) {
    unsigned s = (unsigned)__cvta_generic_to_shared(smem);
    asm volatile("cp.async.cg.shared.global [%0], [%1], 16;" :: "r"(s), "l"(gmem));
}
__device__ __forceinline__ void cp_commit() {
    asm volatile("cp.async.commit_group;");
}
template <int N>
__device__ __forceinline__ void cp_wait() {
    asm volatile("cp.async.wait_group %0;" :: "n"(N));
}

// ---- no-return vector atomic add ----
__device__ __forceinline__ void red_add4(float* p, float x, float y, float z, float w) {
    asm volatile("red.global.add.v4.f32 [%0], {%1, %2, %3, %4};"
                 :: "l"(p), "f"(x), "f"(y), "f"(z), "f"(w) : "memory");
}

// =======================================================================
// K2: partial dots + partial sumsq. grid (125, 7) x 256 threads.
// Block owns 16 memory rows, 28 d-chunks of 128 floats (d-split by grid.y).
// Key chunk (16x128) and mem chunk (16x128) staged via 5-stage cp.async
// pipeline (~3.5 chunks of DRAM latency hidden, zero register cost).
// Dynamic smem: 5 stages x (key 8KB + mem 8KB) = 80KB; 2 blocks/SM.
// This is the fastest measured k_dots (R11, 74.8us); key-stats removed
// from the loop so no block does extra straggler work.
// Lane layout per warp: bit7=bh (which 8 b's), bits[6:5]=u_hi, bits[4:3]=g
// (which 4 n's), bits[2:0]=u_lo. d-lane = u_hi*8+u_lo (4 floats each).
// g in-warp -> key LDS is a 4-way in-warp broadcast.
// =======================================================================
__global__ __launch_bounds__(256, 2) void k_dots(const float* __restrict__ key,
                                                 const float* __restrict__ mem) {
    extern __shared__ __align__(16) float sdyn[];   // KSTG * 4096 floats
    // overlay after the chunk loop: reduction scratch on stage 0
    float* sred = sdyn;          // 256 floats [bh][g][bb][r]
    float* ssq  = sdyn + 256;    // 16 floats  [g][r]

    int tid  = threadIdx.x;
    int bh   = tid >> 7;
    int g    = (tid >> 3) & 3;
    int u_lo = tid & 7;
    int dl   = ((tid >> 5) & 3) * 8 + u_lo;   // d-lane 0..31
    int nb   = blockIdx.x * 16;
    int sy   = blockIdx.y;
    int cbase = sy * CPB;

    unsigned long long acc[8][4];
    #pragma unroll
    for (int i = 0; i < 8; ++i)
        #pragma unroll
        for (int r = 0; r < 4; ++r) acc[i][r] = 0ull;
    unsigned long long sq2[4] = {0ull, 0ull, 0ull, 0ull};

    // staging lanes: thread copies one float4 of 2 key rows + 2 mem rows
    int row0 = tid >> 5;          // 0..7
    int j    = tid & 31;          // float4 within row

    const float* kr0 = key + (size_t)row0 * Dn + j * 4;
    const float* kr1 = key + (size_t)(row0 + 8) * Dn + j * 4;
    const float* mr0 = mem + (size_t)(nb + row0) * Dn + j * 4;
    const float* mr1 = mem + (size_t)(nb + row0 + 8) * Dn + j * 4;

    int so  = row0 * CHUNK + j * 4;        // smem float offset (rows 0..7)
    int so8 = (row0 + 8) * CHUNK + j * 4;  // smem float offset (rows 8..15)

    // prologue: stages 0..3 in flight
    #pragma unroll
    for (int s = 0; s < KSTG - 1; ++s) {
        float* st = sdyn + s * 4096;
        int off = (cbase + s) * CHUNK;
        cp16(st + so,         kr0 + off);
        cp16(st + so8,        kr1 + off);
        cp16(st + 2048 + so,  mr0 + off);
        cp16(st + 2048 + so8, mr1 + off);
        cp_commit();
    }

    int bufc = 0, bufi = KSTG - 1;
    for (int cc = 0; cc < CPB; ++cc) {
        cp_wait<KSTG - 2>();   // stage cc landed
        __syncthreads();       // visible to all; prior compute on bufi done

        if (cc + KSTG - 1 < CPB) {   // issue stage cc+4 into bufi
            float* st = sdyn + bufi * 4096;
            int off = (cbase + cc + KSTG - 1) * CHUNK;
            cp16(st + so,         kr0 + off);
            cp16(st + so8,        kr1 + off);
            cp16(st + 2048 + so,  mr0 + off);
            cp16(st + 2048 + so8, mr1 + off);
        }
        cp_commit();           // commit every iter to keep group accounting
        if (++bufi == KSTG) bufi = 0;

        const float* km = sdyn + bufc * 4096;
        const float* mm = km + 2048;
        if (++bufc == KSTG) bufc = 0;

        ulonglong2 mv[4];
        #pragma unroll
        for (int r = 0; r < 4; ++r)
            mv[r] = *(const ulonglong2*)&mm[(g * 4 + r) * CHUNK + dl * 4];
        if (bh == 0) {
            #pragma unroll
            for (int r = 0; r < 4; ++r) {
                fma2(sq2[r], mv[r].x, mv[r].x);
                fma2(sq2[r], mv[r].y, mv[r].y);
            }
        }
        #pragma unroll
        for (int bb = 0; bb < 8; ++bb) {
            ulonglong2 kv = *(const ulonglong2*)&km[(bh * 8 + bb) * CHUNK + dl * 4];
            #pragma unroll
            for (int r = 0; r < 4; ++r) {
                fma2(acc[bb][r], kv.x, mv[r].x);
                fma2(acc[bb][r], kv.y, mv[r].y);
            }
        }
    }
    __syncthreads();   // all cp groups drained by last wait; safe to overlay
    sred[tid] = 0.f;   // zero overlaid reduction scratch (sred[256] + ssq[16])
    if (tid < 16) ssq[tid] = 0.f;
    __syncthreads();

    // reduce: butterfly over u_lo (8 lanes), then smem-atomic across 4 u_hi warps
    #pragma unroll
    for (int bb = 0; bb < 8; ++bb)
        #pragma unroll
        for (int r = 0; r < 4; ++r) {
            float v = f2lo(acc[bb][r]) + f2hi(acc[bb][r]);
            v += __shfl_xor_sync(0xFFFFFFFFu, v, 1);
            v += __shfl_xor_sync(0xFFFFFFFFu, v, 2);
            v += __shfl_xor_sync(0xFFFFFFFFu, v, 4);
            if (bb == u_lo)
                atomicAdd(&sred[bh * 128 + g * 32 + bb * 4 + r], v);
        }
    if (bh == 0) {
        #pragma unroll
        for (int r = 0; r < 4; ++r) {
            float v = f2lo(sq2[r]) + f2hi(sq2[r]);
            v += __shfl_xor_sync(0xFFFFFFFFu, v, 1);
            v += __shfl_xor_sync(0xFFFFFFFFu, v, 2);
            v += __shfl_xor_sync(0xFFFFFFFFu, v, 4);
            if (u_lo == r) atomicAdd(&ssq[g * 4 + r], v);
        }
    }
    __syncthreads();

    {   // write 256 partial dots
        int r = tid & 3, bb = (tid >> 2) & 7, gg = (tid >> 5) & 3, b2 = tid >> 7;
        int b = b2 * 8 + bb, n = nb + gg * 4 + r;
        g_dotp[((size_t)sy * Bn + b) * Nn + n] = sred[b2 * 128 + gg * 32 + bb * 4 + r];
    }
    if (tid < 16) {
        int r = tid & 3, gg = tid >> 2;
        g_sqp[(size_t)sy * Nn + nb + gg * 4 + r] = ssq[gg * 4 + r];
    }
}

// ============================================================
// K3: key stats (block b reduces its own key row) -> sum dot
// partials -> cos -> tan -> softmax; write transposed duplicated
// weights (w,w). Also zeroes d_out. grid 16 x 256.
// ============================================================
__global__ void k_softmax(const float* __restrict__ key, float* __restrict__ out) {
    int b = blockIdx.x, tid = threadIdx.x;
    __shared__ float sbuf[256];
    __shared__ float swq[8], sws[8];
    __shared__ float s_kfac;

    {   // zero this block's slice of the output (Bn*Dn floats over 16 blocks)
        float4 z = make_float4(0.f, 0.f, 0.f, 0.f);
        float4* o4 = (float4*)(out + (size_t)b * Dn);
        for (int i = tid; i < Dn / 4; i += 256) o4[i] = z;
    }

    {   // key stats: sum and sumsq of key row b (6272 float4)
        const float4* kp = (const float4*)(key + (size_t)b * Dn);
        float s = 0.f, q = 0.f;
        for (int i = tid; i < Dn / 4; i += 256) {
            float4 v = kp[i];
            s += (v.x + v.y) + (v.z + v.w);
            q = fmaf(v.x, v.x, q); q = fmaf(v.y, v.y, q);
            q = fmaf(v.z, v.z, q); q = fmaf(v.w, v.w, q);
        }
        #pragma unroll
        for (int o = 16; o; o >>= 1) {
            s += __shfl_xor_sync(0xFFFFFFFFu, s, o);
            q += __shfl_xor_sync(0xFFFFFFFFu, q, o);
        }
        if ((tid & 31) == 0) { sws[tid >> 5] = s; swq[tid >> 5] = q; }
        __syncthreads();
        if (tid == 0) {
            float S = 0.f, Q = 0.f;
            #pragma unroll
            for (int i = 0; i < 8; ++i) { S += sws[i]; Q += swq[i]; }
            S += 1e-7f;                               // EPS_SUM
            // (s+eps)*kn = max(sqrt(sq_key), 1e-8*(s+eps))
            s_kfac = 1.f / fmaxf(sqrtf(Q), 1e-8f * S);
        }
        __syncthreads();
    }
    float kf = s_kfac;

    float tv[8];
    float mx = -3.4e38f;
    #pragma unroll
    for (int i = 0; i < 8; ++i) {
        int n = tid + i * 256;
        if (n < Nn) {
            float dot = 0.f, sqv = 0.f;
            #pragma unroll
            for (int p = 0; p < DSPLIT; ++p) {
                dot += g_dotp[((size_t)p * Bn + b) * Nn + n];
                sqv += g_sqp[(size_t)p * Nn + n];
            }
            float mn = fmaxf(sqrtf(sqv), 1e-8f);
            float cosv = dot * kf / mn;
            float t = tanf(cosv * PI2F);
            tv[i] = t;
            mx = fmaxf(mx, t);
        } else tv[i] = -3.4e38f;
    }
    sbuf[tid] = mx; __syncthreads();
    for (int s = 128; s; s >>= 1) {
        if (tid < s) sbuf[tid] = fmaxf(sbuf[tid], sbuf[tid + s]);
        __syncthreads();
    }
    mx = sbuf[0];
    __syncthreads();

    float sum = 0.f;
    #pragma unroll
    for (int i = 0; i < 8; ++i) {
        int n = tid + i * 256;
        if (n < Nn) { float e = expf(tv[i] - mx); tv[i] = e; sum += e; }
    }
    sbuf[tid] = sum; __syncthreads();
    for (int s = 128; s; s >>= 1) {
        if (tid < s) sbuf[tid] += sbuf[tid + s];
        __syncthreads();
    }
    float inv = 1.f / sbuf[0];

    #pragma unroll
    for (int i = 0; i < 8; ++i) {
        int n = tid + i * 256;
        if (n < Nn) {
            float w = tv[i] * inv;
            g_w2[(size_t)n * Bn + b] = make_float2(w, w);  // pre-duplicated pair
        }
    }
}

// =======================================================================
// K4: out[b][d] = sum_n w[b][n] * mem[n][d]. grid (49, 12) x 128 threads.
// 588 blocks = exactly one occ-4 wave (592 slots on 148 SMs).
// Thread owns 4 consecutive d; 16 b accumulators as f32x2 pairs.
// Mem rows flow through a per-thread 12-stage cp.async pipeline (11 rows of
// DRAM latency in flight, no barriers). Weight tile staged in smem once.
// Partials combined via red.global.add.v4.f32 (no-return vector atomic).
// =======================================================================
__global__ __launch_bounds__(128, 4) void k_read(const float* __restrict__ mem,
                                                 float* __restrict__ out) {
    __shared__ __align__(16) ulonglong2 sw[167 * 8];     // 21376 B weight tile
    __shared__ __align__(16) char smrow[RSTG][2048];     // 24 KB pipeline

    int tid = threadIdx.x;
    int d   = blockIdx.x * 512 + tid * 4;
    int y   = blockIdx.y;
    int n0  = (y < 8) ? y * 167 : 1336 + (y - 8) * 166;
    int cnt = (y < 8) ? 167 : 166;

    // stage weight tile: cnt x 128B
    {
        const float4* src = (const float4*)(g_w2 + (size_t)n0 * Bn);
        for (int i = tid; i < cnt * 8; i += 128)
            ((float4*)sw)[i] = src[i];
    }

    unsigned long long acc[16][2];
    #pragma unroll
    for (int b = 0; b < 16; ++b) { acc[b][0] = 0ull; acc[b][1] = 0ull; }

    const float* mp = mem + (size_t)n0 * Dn + d;
    // prologue: 11 rows in flight (cnt >= 166 always)
    #pragma unroll
    for (int s = 0; s < RSTG - 1; ++s) {
        cp16(&smrow[s][tid * 16], mp + (size_t)s * Dn);
        cp_commit();
    }
    const float* pf = mp + (size_t)(RSTG - 1) * Dn;
    __syncthreads();   // weight tile ready

    int slc = 0, sli = RSTG - 1;
    for (int n = 0; n < cnt; ++n) {
        cp_wait<RSTG - 2>();  // per-thread: stage n landed
        ulonglong2 cur = *(const ulonglong2*)&smrow[slc][tid * 16];
        if (++slc == RSTG) slc = 0;
        if (n + RSTG - 1 < cnt) cp16(&smrow[sli][tid * 16], pf);
        cp_commit();
        if (++sli == RSTG) sli = 0;
        pf += Dn;
        const ulonglong2* wq = sw + n * 8;
        #pragma unroll
        for (int q = 0; q < 8; ++q) {
            ulonglong2 wv = wq[q];                // (w2q,w2q),(w2q+1,w2q+1)
            fma2(acc[2 * q    ][0], wv.x, cur.x);
            fma2(acc[2 * q    ][1], wv.x, cur.y);
            fma2(acc[2 * q + 1][0], wv.y, cur.x);
            fma2(acc[2 * q + 1][1], wv.y, cur.y);
        }
    }

    #pragma unroll
    for (int b = 0; b < 16; ++b) {
        float* o = out + (size_t)b * Dn + d;
        red_add4(o, f2lo(acc[b][0]), f2hi(acc[b][0]),
                    f2lo(acc[b][1]), f2hi(acc[b][1]));
    }
}

// ============================================================
extern "C" void kernel_launch(void* const* d_in, const int* in_sizes, int n_in,
                              void* d_out, int out_size) {
    const float* key = (const float*)d_in[0];
    const float* mem = (const float*)d_in[1];
    // metadata order is key, memory; swap defensively if sizes say otherwise
    if (n_in >= 2 && in_sizes[0] == Nn * Dn) {
        key = (const float*)d_in[1];
        mem = (const float*)d_in[0];
    }
    float* out = (float*)d_out;

    // 80KB dynamic smem for k_dots (attribute persists from the harness's
    // non-captured correctness call, so capture-time behavior is identical)
    const int kdots_smem = KSTG * 4096 * (int)sizeof(float);
    cudaFuncSetAttribute(k_dots, cudaFuncAttributeMaxDynamicSharedMemorySize,
                         kdots_smem);

    k_dots<<<dim3(125, DSPLIT), 256, kdots_smem>>>(key, mem);
    k_softmax<<<16, 256>>>(key, out);  // key stats + softmax + zeroes out
    k_read<<<dim3(49, 12), 128>>>(mem, out);
}